// round 2
// baseline (speedup 1.0000x reference)
#include <cuda_runtime.h>
#include <cstddef>

// Correlation layer: out[b, ix*21+iy, h, w] = sum_c f1[b,c,h,w] * f2[b,c,h+2ix-20, w+2iy-20]
// B=4, C=128, H=96, W=192, D=20, stride 2 -> 21x21 offsets.
//
// Parity trick: w and w+2*iy-20 share parity. Split rows into even/odd parity
// arrays; the stride-2 correlation becomes a dense 21-tap FIR over the
// parity-compressed index u (w = 2u+p):
//   out[u][iy] += f1[u] * f2p[u + iy - 10]
// Thread owns Ut=4 consecutive u of one parity: 84 accumulators, reads
// 4 f1 + 24 contiguous f2 floats per channel (7 x LDS.128) for 84 FMA.
// Block = (h, b, ix-group-of-7); smem double-buffered, LDG prefetch into regs.

#define CC        4                    // channels per smem chunk
#define NTHR      336                  // 7 ix-subgroups * 48 cols
#define S1_FLOATS (CC * 2 * 96)        // [c][parity][96]
#define S2_FLOATS (CC * 7 * 2 * 120)   // [c][q][parity][120]  (116 used, pad 120)
#define BUF_FLOATS (S1_FLOATS + S2_FLOATS)   // 7488 floats = 29952 B
#define S2OFF     S1_FLOATS
#define TOTAL_F2  (CC * 96 + CC * 7 * 120)   // 3744 float2 loads per chunk
#define NL        12                   // ceil(3744/336)

__global__ void __launch_bounds__(NTHR, 1)
corr_kernel(const float* __restrict__ f1, const float* __restrict__ f2,
            float* __restrict__ out)
{
    extern __shared__ float smem[];

    const int h   = blockIdx.x;   // 0..95
    const int b   = blockIdx.y;   // 0..3
    const int ixg = blockIdx.z;   // 0..2  (covers ix = 7*ixg + q)
    const int tid = threadIdx.x;

    const int q   = tid / 48;          // 0..6 : which ix in this group
    const int col = tid % 48;
    const int p   = col / 24;          // parity of w
    const int u0  = (col % 24) * 4;    // first parity-index handled

    const int ix     = ixg * 7 + q;
    const int h2base = h - 20 + 14 * ixg;  // h + 2*(7*ixg) - 20

    float acc[84];
    #pragma unroll
    for (int i = 0; i < 84; i++) acc[i] = 0.0f;

    float2 v[NL];   // register prefetch slots

    auto load_chunk = [&](int c0) {
        #pragma unroll
        for (int i = 0; i < NL; i++) {
            int idx = tid + i * NTHR;
            float2 val = make_float2(0.0f, 0.0f);
            if (idx < TOTAL_F2) {
                if (idx < CC * 96) {
                    // f1 row: load float2 at w = 2u
                    int c = idx / 96;
                    int u = idx - c * 96;
                    val = *reinterpret_cast<const float2*>(
                        f1 + (((size_t)(b * 128 + c0 + c)) * 96 + h) * 192 + 2 * u);
                } else {
                    // f2 rows: phys slot s in [0,120), u' = s-10, w_even = 2s-20
                    int t  = idx - CC * 96;
                    int c  = t / 840;
                    int r  = t - c * 840;
                    int qq = r / 120;
                    int s  = r - qq * 120;
                    int h2 = h2base + 2 * qq;
                    int w0 = 2 * s - 20;
                    if (s < 116 && (unsigned)h2 < 96u && (unsigned)w0 < 192u)
                        val = *reinterpret_cast<const float2*>(
                            f2 + (((size_t)(b * 128 + c0 + c)) * 96 + h2) * 192 + w0);
                }
            }
            v[i] = val;
        }
    };

    auto store_chunk = [&](float* buf) {
        #pragma unroll
        for (int i = 0; i < NL; i++) {
            int idx = tid + i * NTHR;
            if (idx < TOTAL_F2) {
                if (idx < CC * 96) {
                    int c = idx / 96;
                    int u = idx - c * 96;
                    buf[(c * 2 + 0) * 96 + u] = v[i].x;   // even parity
                    buf[(c * 2 + 1) * 96 + u] = v[i].y;   // odd parity
                } else {
                    int t  = idx - CC * 96;
                    int c  = t / 840;
                    int r  = t - c * 840;
                    int qq = r / 120;
                    int s  = r - qq * 120;
                    float* base = buf + S2OFF + ((c * 7 + qq) * 2) * 120 + s;
                    base[0]   = v[i].x;   // even parity
                    base[120] = v[i].y;   // odd parity
                }
            }
        }
    };

    // prologue: fill buffer 0 with chunk 0
    load_chunk(0);
    store_chunk(smem);
    __syncthreads();

    const int NCHUNK = 128 / CC;   // 32
    #pragma unroll 1
    for (int cc = 0; cc < NCHUNK; cc++) {
        const float* cur = smem + (cc & 1) * BUF_FLOATS;
        float*       nxt = smem + ((cc + 1) & 1) * BUF_FLOATS;

        if (cc + 1 < NCHUNK) load_chunk((cc + 1) * CC);   // LDGs in flight over compute

        #pragma unroll
        for (int c = 0; c < CC; c++) {
            float4 v1 = *reinterpret_cast<const float4*>(cur + (c * 2 + p) * 96 + u0);
            const float4* p2 = reinterpret_cast<const float4*>(
                cur + S2OFF + ((c * 7 + q) * 2 + p) * 120 + u0);
            float4 A = p2[0], B4 = p2[1], C4 = p2[2], D4 = p2[3], E4 = p2[4], F4 = p2[5];
            float r2[24] = {A.x,  A.y,  A.z,  A.w,  B4.x, B4.y, B4.z, B4.w,
                            C4.x, C4.y, C4.z, C4.w, D4.x, D4.y, D4.z, D4.w,
                            E4.x, E4.y, E4.z, E4.w, F4.x, F4.y, F4.z, F4.w};
            float v1a[4] = {v1.x, v1.y, v1.z, v1.w};
            #pragma unroll
            for (int k = 0; k < 4; k++) {
                float fv = v1a[k];
                #pragma unroll
                for (int j = 0; j < 21; j++)
                    acc[k * 21 + j] = fmaf(fv, r2[k + j], acc[k * 21 + j]);
            }
        }

        if (cc + 1 < NCHUNK) store_chunk(nxt);
        __syncthreads();
    }

    // write: out[((b*441 + ix*21 + j)*96 + h)*192 + w], w = 2*(u0+k)+p
    const int wbase = 2 * u0 + p;
    size_t base = (((size_t)b * 441 + (size_t)ix * 21) * 96 + h) * 192;
    #pragma unroll
    for (int j = 0; j < 21; j++) {
        size_t ob = base + (size_t)j * (96 * 192) + wbase;
        #pragma unroll
        for (int k = 0; k < 4; k++)
            out[ob + 2 * k] = acc[k * 21 + j];
    }
}

extern "C" void kernel_launch(void* const* d_in, const int* in_sizes, int n_in,
                              void* d_out, int out_size)
{
    const float* f1 = (const float*)d_in[0];
    const float* f2 = (const float*)d_in[1];
    float* out = (float*)d_out;

    size_t smem_bytes = (size_t)2 * BUF_FLOATS * sizeof(float);  // 59904 B
    cudaFuncSetAttribute(corr_kernel, cudaFuncAttributeMaxDynamicSharedMemorySize,
                         (int)smem_bytes);

    dim3 grid(96, 4, 3);   // (h, b, ix-group)
    corr_kernel<<<grid, NTHR, smem_bytes>>>(f1, f2, out);
}